// round 1
// baseline (speedup 1.0000x reference)
#include <cuda_runtime.h>
#include <math.h>

// ============================================================================
// HolomorphicEqProp — fp32 SIMT baseline (round 1)
//
//   sigma(W,u) = ||W v||,  v = (W^T u)/(||W^T u||+eps)      (analytic simplification)
//   x_proj = x @ (W_in/s_in)^T + b_in
//   h_{t+1} = tanh(x_proj + (h_t @ (W_rec/s_rec)^T + b_rec) * (1+0.1 sin(0.3 t)))
//   out = h_30 @ (W_out/s_out)^T + b_out
//
// All GEMMs are NT (both operands K-contiguous). Epilogue fully fused.
// ============================================================================

#define BM 128
#define BN 128
#define BK 8
#define TM 8
#define TN 8
#define NSTEPS 30

// Static scratch (no allocations allowed)
__device__ float g_xproj[4096 * 1024];
__device__ float g_h[2][4096 * 1024];
__device__ float g_y[1024];
__device__ float g_v[1024];
__device__ float g_z[1024];
__device__ float g_invsig[3];

// ---------------------------------------------------------------------------
// block reduction helper
// ---------------------------------------------------------------------------
__device__ __forceinline__ float block_reduce_sum(float v) {
    __shared__ float sh[32];
    int lane = threadIdx.x & 31, w = threadIdx.x >> 5;
    #pragma unroll
    for (int o = 16; o; o >>= 1) v += __shfl_xor_sync(0xffffffffu, v, o);
    if (!lane) sh[w] = v;
    __syncthreads();
    int nw = blockDim.x >> 5;
    v = (threadIdx.x < nw) ? sh[threadIdx.x] : 0.0f;
    if (w == 0) {
        #pragma unroll
        for (int o = 16; o; o >>= 1) v += __shfl_xor_sync(0xffffffffu, v, o);
        if (!lane) sh[0] = v;
    }
    __syncthreads();
    return sh[0];
}

// ---------------------------------------------------------------------------
// spectral-norm kernels (tiny cost)
// ---------------------------------------------------------------------------
__global__ void zero_kernel(float* p, int n) {
    int i = blockIdx.x * blockDim.x + threadIdx.x;
    if (i < n) p[i] = 0.0f;
}

// y[c] += sum_{r in slice} W[r,C..]*u[r]   (grid.y slices, atomic combine)
__global__ void colmv_kernel(const float* __restrict__ W, const float* __restrict__ u,
                             float* __restrict__ y, int R, int C) {
    int c = blockIdx.x * blockDim.x + threadIdx.x;
    if (c >= C) return;
    int per = R / gridDim.y;
    int r0 = blockIdx.y * per;
    int r1 = (blockIdx.y == gridDim.y - 1) ? R : r0 + per;
    float acc = 0.0f;
    for (int r = r0; r < r1; r++) acc += W[(long)r * C + c] * u[r];
    atomicAdd(&y[c], acc);
}

// v = y / (||y|| + 1e-12)
__global__ void normalize_kernel(const float* __restrict__ y, float* __restrict__ v, int n) {
    float ss = 0.0f;
    for (int i = threadIdx.x; i < n; i += blockDim.x) { float t = y[i]; ss += t * t; }
    float tot = block_reduce_sum(ss);
    float scale = 1.0f / (sqrtf(tot) + 1e-12f);
    for (int i = threadIdx.x; i < n; i += blockDim.x) v[i] = y[i] * scale;
}

// z[r] = sum_c W[r,c]*v[c]   (warp per row)
__global__ void rowmv_kernel(const float* __restrict__ W, const float* __restrict__ v,
                             float* __restrict__ z, int R, int C) {
    int warp = (blockIdx.x * blockDim.x + threadIdx.x) >> 5;
    int lane = threadIdx.x & 31;
    if (warp >= R) return;
    float acc = 0.0f;
    for (int c = lane; c < C; c += 32) acc += W[(long)warp * C + c] * v[c];
    #pragma unroll
    for (int o = 16; o; o >>= 1) acc += __shfl_xor_sync(0xffffffffu, acc, o);
    if (!lane) z[warp] = acc;
}

// invsig = 1/sigma,  sigma = ||z||^2 / (||z|| + 1e-12)   (matches reference exactly)
__global__ void sigma_kernel(const float* __restrict__ z, float* __restrict__ invsig, int n) {
    float ss = 0.0f;
    for (int i = threadIdx.x; i < n; i += blockDim.x) { float t = z[i]; ss += t * t; }
    float tot = block_reduce_sum(ss);
    if (threadIdx.x == 0) {
        float nz = sqrtf(tot);
        invsig[0] = (nz + 1e-12f) / tot;   // 1 / (tot/(nz+eps))
    }
}

// ---------------------------------------------------------------------------
// step 0: h = tanh(x_proj + b_rec * mod)   (h0 == 0, GEMM skipped)
// ---------------------------------------------------------------------------
__global__ void step0_kernel(const float* __restrict__ xproj, const float* __restrict__ brec,
                             float* __restrict__ h, long total, int H, float mod,
                             const int* __restrict__ steps) {
    long i = (long)blockIdx.x * blockDim.x + threadIdx.x;
    if (i >= total) return;
    int col = (int)(i % H);
    float val = (0 < *steps) ? tanhf(xproj[i] + brec[col] * mod) : 0.0f;
    h[i] = val;
}

// ---------------------------------------------------------------------------
// fused NT SGEMM:  C = epilogue( A[M,K] @ Bw[N,K]^T )
//   STEP=false:  C = acc*invsig + bias[col]
//   STEP=true :  C = tanh(xproj + (acc*invsig + bias[col])*mod)   (or passthrough)
// ---------------------------------------------------------------------------
template <bool STEP>
__global__ __launch_bounds__(256)
void gemm_nt_kernel(const float* __restrict__ A, const float* __restrict__ Bw,
                    const float* __restrict__ bias, const float* __restrict__ invsig,
                    float* __restrict__ C, int M, int N, int K,
                    const float* __restrict__ xproj, const float* __restrict__ hold,
                    float mod, int t, const int* __restrict__ steps) {
    __shared__ float As[BK][BM];
    __shared__ float Bs[BK][BN];

    const int tid = threadIdx.x;
    const int bm = blockIdx.y * BM;
    const int bn = blockIdx.x * BN;
    const int tx = tid & 15;       // 16 cols of threads
    const int ty = tid >> 4;       // 16 rows of threads

    const int lrow = tid >> 1;         // 0..127
    const int lseg = (tid & 1) * 4;    // 0 or 4

    const float* Aptr = A + (long)(bm + lrow) * K + lseg;
    const float* Bptr = Bw + (long)(bn + lrow) * K + lseg;

    float acc[TM][TN];
    #pragma unroll
    for (int i = 0; i < TM; i++)
        #pragma unroll
        for (int j = 0; j < TN; j++) acc[i][j] = 0.0f;

    for (int k0 = 0; k0 < K; k0 += BK) {
        float4 av = *(const float4*)(Aptr + k0);
        float4 bv = *(const float4*)(Bptr + k0);
        __syncthreads();
        As[lseg + 0][lrow] = av.x; As[lseg + 1][lrow] = av.y;
        As[lseg + 2][lrow] = av.z; As[lseg + 3][lrow] = av.w;
        Bs[lseg + 0][lrow] = bv.x; Bs[lseg + 1][lrow] = bv.y;
        Bs[lseg + 2][lrow] = bv.z; Bs[lseg + 3][lrow] = bv.w;
        __syncthreads();

        #pragma unroll
        for (int k = 0; k < BK; k++) {
            float a[TM], b[TN];
            #pragma unroll
            for (int i = 0; i < TM; i++) a[i] = As[k][ty * TM + i];
            #pragma unroll
            for (int j = 0; j < TN; j++) b[j] = Bs[k][tx * TN + j];
            #pragma unroll
            for (int i = 0; i < TM; i++)
                #pragma unroll
                for (int j = 0; j < TN; j++) acc[i][j] += a[i] * b[j];
        }
    }

    const float sig = *invsig;
    int st = 0;
    if (STEP) st = *steps;

    #pragma unroll
    for (int i = 0; i < TM; i++) {
        const int row = bm + ty * TM + i;
        #pragma unroll
        for (int j = 0; j < TN; j++) {
            const int col = bn + tx * TN + j;
            const long idx = (long)row * N + col;
            float val = acc[i][j] * sig + bias[col];
            if (STEP) {
                if (t < st) val = tanhf(xproj[idx] + val * mod);
                else        val = hold[idx];   // steps exceeded: identity
            }
            C[idx] = val;
        }
    }
}

// ---------------------------------------------------------------------------
// launch
// ---------------------------------------------------------------------------
extern "C" void kernel_launch(void* const* d_in, const int* in_sizes, int n_in,
                              void* d_out, int out_size) {
    const float* x     = (const float*)d_in[0];
    const float* W_in  = (const float*)d_in[1];
    const float* b_in  = (const float*)d_in[2];
    const float* W_rec = (const float*)d_in[3];
    const float* b_rec = (const float*)d_in[4];
    const float* W_out = (const float*)d_in[5];
    const float* b_out = (const float*)d_in[6];
    const float* u_in  = (const float*)d_in[7];
    const float* u_rec = (const float*)d_in[8];
    const float* u_out = (const float*)d_in[9];
    const int*   steps = (const int*)d_in[10];

    const int H    = in_sizes[2];
    const int DIN  = in_sizes[1] / H;
    const int B    = in_sizes[0] / DIN;
    const int DOUT = in_sizes[6];

    float *xproj, *hbase, *y, *v, *z, *invsig;
    cudaGetSymbolAddress((void**)&xproj,  g_xproj);
    cudaGetSymbolAddress((void**)&hbase,  g_h);
    cudaGetSymbolAddress((void**)&y,      g_y);
    cudaGetSymbolAddress((void**)&v,      g_v);
    cudaGetSymbolAddress((void**)&z,      g_z);
    cudaGetSymbolAddress((void**)&invsig, g_invsig);
    float* hbuf[2] = { hbase, hbase + (long)4096 * 1024 };

    // --- spectral sigma for the three matrices ---
    auto spectral = [&](const float* W, const float* u, int R, int C, int idx) {
        zero_kernel<<<(C + 255) / 256, 256>>>(y, C);
        colmv_kernel<<<dim3((C + 127) / 128, 8), 128>>>(W, u, y, R, C);
        normalize_kernel<<<1, 256>>>(y, v, C);
        rowmv_kernel<<<(R + 7) / 8, 256>>>(W, v, z, R, C);
        sigma_kernel<<<1, 256>>>(z, invsig + idx, R);
    };
    spectral(W_in,  u_in,  H,    DIN, 0);
    spectral(W_rec, u_rec, H,    H,   1);
    spectral(W_out, u_out, DOUT, H,   2);

    // --- x_proj = x @ (W_in/s)^T + b_in ---
    gemm_nt_kernel<false><<<dim3(H / BN, B / BM), 256>>>(
        x, W_in, b_in, invsig + 0, xproj, B, H, DIN,
        nullptr, nullptr, 0.0f, 0, nullptr);

    // --- step 0 (h0 = 0): elementwise ---
    {
        long total = (long)B * H;
        float mod0 = 1.0f + 0.1f * sinf(0.3f * 0.0f);
        step0_kernel<<<(int)((total + 255) / 256), 256>>>(
            xproj, b_rec, hbuf[0], total, H, mod0, steps);
    }

    // --- steps 1..29: fused GEMM + tanh epilogue, ping-pong ---
    int cur = 0;
    for (int t = 1; t < NSTEPS; t++) {
        float mod = 1.0f + 0.1f * sinf(0.3f * (float)t);
        gemm_nt_kernel<true><<<dim3(H / BN, B / BM), 256>>>(
            hbuf[cur], W_rec, b_rec, invsig + 1, hbuf[1 - cur], B, H, H,
            xproj, hbuf[cur], mod, t, steps);
        cur ^= 1;
    }

    // --- out = h @ (W_out/s)^T + b_out ---
    gemm_nt_kernel<false><<<dim3(DOUT / BN, B / BM), 256>>>(
        hbuf[cur], W_out, b_out, invsig + 2, (float*)d_out, B, DOUT, H,
        nullptr, nullptr, 0.0f, 0, nullptr);
}

// round 3
// speedup vs baseline: 2.5576x; 2.5576x over previous
#include <cuda_runtime.h>
#include <cuda_bf16.h>
#include <math.h>
#include <stdint.h>

// ============================================================================
// HolomorphicEqProp — mma.sync bf16 hi/lo split GEMM (round 3)
//   (tcgen05 unusable: harness emits compute_103 PTX, arch-specific ops rejected)
//   D = Ahi*Bhi + Alo*Bhi + Ahi*Blo   (fp32 accumulate)  ~ fp32 accuracy
// ============================================================================

#define H_DIM   1024
#define B_DIM   4096
#define NSTEPS  30

// ---------------------------------------------------------------------------
// helpers
// ---------------------------------------------------------------------------
__device__ __forceinline__ uint32_t smem_u32(const void* p) {
    uint32_t a;
    asm("{ .reg .u64 t; cvta.to.shared.u64 t, %1; cvt.u32.u64 %0, t; }" : "=r"(a) : "l"(p));
    return a;
}
__device__ __forceinline__ void cp_async16(uint32_t saddr, const void* g) {
    asm volatile("cp.async.cg.shared.global [%0], [%1], 16;" :: "r"(saddr), "l"(g));
}
#define CP_COMMIT() asm volatile("cp.async.commit_group;" ::: "memory")
#define CP_WAIT1()  asm volatile("cp.async.wait_group 1;" ::: "memory")
#define CP_WAIT0()  asm volatile("cp.async.wait_group 0;" ::: "memory")

__device__ __forceinline__ void ldm_x4(uint32_t* r, uint32_t addr) {
    asm volatile("ldmatrix.sync.aligned.m8n8.x4.shared.b16 {%0,%1,%2,%3}, [%4];"
                 : "=r"(r[0]), "=r"(r[1]), "=r"(r[2]), "=r"(r[3]) : "r"(addr));
}
__device__ __forceinline__ void mma16816(float* c, const uint32_t* a, uint32_t b0, uint32_t b1) {
    asm volatile("mma.sync.aligned.m16n8k16.row.col.f32.bf16.bf16.f32 "
                 "{%0,%1,%2,%3}, {%4,%5,%6,%7}, {%8,%9}, {%0,%1,%2,%3};"
                 : "+f"(c[0]), "+f"(c[1]), "+f"(c[2]), "+f"(c[3])
                 : "r"(a[0]), "r"(a[1]), "r"(a[2]), "r"(a[3]), "r"(b0), "r"(b1));
}

// SW128-style placement: two 64-byte k-rows share one 128B smem row.
// row in [0,128), seg in [0,4) (16B units of the 32-elem k chunk).
// Conflict-free for 16B stores and all ldmatrix 8-row phases.
__device__ __forceinline__ uint32_t swz(int row, int seg) {
    return ((row >> 1) << 7) + (((((row & 1) << 2) | seg) ^ ((row >> 1) & 7)) << 4);
}

// ---------------------------------------------------------------------------
// static scratch
// ---------------------------------------------------------------------------
__device__ __nv_bfloat16 g_xhi[B_DIM * H_DIM], g_xlo[B_DIM * H_DIM];
__device__ __nv_bfloat16 g_wih[H_DIM * H_DIM], g_wil[H_DIM * H_DIM];
__device__ __nv_bfloat16 g_wrh[H_DIM * H_DIM], g_wrl[H_DIM * H_DIM];
__device__ __nv_bfloat16 g_woh[256 * H_DIM],  g_wol[256 * H_DIM];
__device__ float g_xproj[B_DIM * H_DIM];
__device__ __nv_bfloat16 g_hhi[2][B_DIM * H_DIM], g_hlo[2][B_DIM * H_DIM];
__device__ float g_y[H_DIM], g_v[H_DIM], g_z[H_DIM], g_invsig[3];

// ---------------------------------------------------------------------------
// spectral norm (tiny)
// ---------------------------------------------------------------------------
__device__ __forceinline__ float block_reduce_sum(float v) {
    __shared__ float sh[32];
    int lane = threadIdx.x & 31, w = threadIdx.x >> 5;
    #pragma unroll
    for (int o = 16; o; o >>= 1) v += __shfl_xor_sync(0xffffffffu, v, o);
    if (!lane) sh[w] = v;
    __syncthreads();
    int nw = blockDim.x >> 5;
    v = (threadIdx.x < nw) ? sh[threadIdx.x] : 0.0f;
    if (w == 0) {
        #pragma unroll
        for (int o = 16; o; o >>= 1) v += __shfl_xor_sync(0xffffffffu, v, o);
        if (!lane) sh[0] = v;
    }
    __syncthreads();
    return sh[0];
}

__global__ void zero_kernel(float* p, int n) {
    int i = blockIdx.x * blockDim.x + threadIdx.x;
    if (i < n) p[i] = 0.0f;
}
__global__ void colmv_kernel(const float* __restrict__ W, const float* __restrict__ u,
                             float* __restrict__ y, int R, int C) {
    int c = blockIdx.x * blockDim.x + threadIdx.x;
    if (c >= C) return;
    int per = R / gridDim.y;
    int r0 = blockIdx.y * per;
    int r1 = (blockIdx.y == gridDim.y - 1) ? R : r0 + per;
    float acc = 0.0f;
    for (int r = r0; r < r1; r++) acc += W[(long)r * C + c] * u[r];
    atomicAdd(&y[c], acc);
}
__global__ void normalize_kernel(const float* __restrict__ y, float* __restrict__ v, int n) {
    float ss = 0.0f;
    for (int i = threadIdx.x; i < n; i += blockDim.x) { float t = y[i]; ss += t * t; }
    float tot = block_reduce_sum(ss);
    float scale = 1.0f / (sqrtf(tot) + 1e-12f);
    for (int i = threadIdx.x; i < n; i += blockDim.x) v[i] = y[i] * scale;
}
__global__ void rowmv_kernel(const float* __restrict__ W, const float* __restrict__ v,
                             float* __restrict__ z, int R, int C) {
    int warp = (blockIdx.x * blockDim.x + threadIdx.x) >> 5;
    int lane = threadIdx.x & 31;
    if (warp >= R) return;
    float acc = 0.0f;
    for (int c = lane; c < C; c += 32) acc += W[(long)warp * C + c] * v[c];
    #pragma unroll
    for (int o = 16; o; o >>= 1) acc += __shfl_xor_sync(0xffffffffu, acc, o);
    if (!lane) z[warp] = acc;
}
__global__ void sigma_kernel(const float* __restrict__ z, float* __restrict__ invsig, int n) {
    float ss = 0.0f;
    for (int i = threadIdx.x; i < n; i += blockDim.x) { float t = z[i]; ss += t * t; }
    float tot = block_reduce_sum(ss);
    if (threadIdx.x == 0) {
        float nz = sqrtf(tot);
        invsig[0] = (nz + 1e-12f) / tot;
    }
}

// ---------------------------------------------------------------------------
// fp32 -> bf16 hi/lo split
// ---------------------------------------------------------------------------
__global__ void split_kernel(const float* __restrict__ s, __nv_bfloat16* __restrict__ hi,
                             __nv_bfloat16* __restrict__ lo, long n) {
    long i = (long)blockIdx.x * blockDim.x + threadIdx.x;
    if (i >= n) return;
    float f = s[i];
    __nv_bfloat16 h = __float2bfloat16(f);
    hi[i] = h;
    lo[i] = __float2bfloat16(f - __bfloat162float(h));
}

// step 0 (h0 = 0): h1 = tanh(xproj + b_rec*mod) -> hi/lo
__global__ void step0_kernel(const float* __restrict__ xproj, const float* __restrict__ brec,
                             __nv_bfloat16* __restrict__ hhi, __nv_bfloat16* __restrict__ hlo,
                             long total, int H, float mod, const int* __restrict__ steps) {
    long i = (long)blockIdx.x * blockDim.x + threadIdx.x;
    if (i >= total) return;
    float val = (0 < *steps) ? tanhf(xproj[i] + brec[i % H] * mod) : 0.0f;
    __nv_bfloat16 h = __float2bfloat16(val);
    hhi[i] = h;
    hlo[i] = __float2bfloat16(val - __bfloat162float(h));
}

// ---------------------------------------------------------------------------
// mma.sync split-bf16 GEMM: C[128x128 tile] = A[M,K] @ B[N,K]^T + epilogue
//   8 warps, warp tile 64x32, K chunks of 32 double-buffered via cp.async.
//   SMEM per stage: 4 matrices (Ahi, Alo, Bhi, Blo) x 8KB = 32KB; 2 stages.
// ---------------------------------------------------------------------------
#define STAGE_B 32768
#define GEMM_SMEM (2 * STAGE_B)

template <bool STEP>
__global__ __launch_bounds__(256, 2)
void mma_gemm(const __nv_bfloat16* __restrict__ Ahi, const __nv_bfloat16* __restrict__ Alo,
              const __nv_bfloat16* __restrict__ Bhi, const __nv_bfloat16* __restrict__ Blo,
              const float* __restrict__ bias, const float* __restrict__ invsig,
              int K, int N,
              float* __restrict__ Cf32,
              __nv_bfloat16* __restrict__ Chi, __nv_bfloat16* __restrict__ Clo,
              const float* __restrict__ xproj,
              const __nv_bfloat16* __restrict__ Hhi_old, const __nv_bfloat16* __restrict__ Hlo_old,
              float mod, int t, const int* __restrict__ steps) {
    extern __shared__ char sm[];
    const uint32_t sbase = smem_u32(sm);

    const int tid  = threadIdx.x;
    const int wid  = tid >> 5;
    const int lane = tid & 31;
    const int bm   = blockIdx.y * 128;
    const int bn   = blockIdx.x * 128;
    const int wm   = (wid >> 2) * 64;      // warp m offset in tile
    const int wn   = (wid & 3) * 32;       // warp n offset in tile

    const __nv_bfloat16* src[4] = {
        Ahi + (size_t)bm * K, Alo + (size_t)bm * K,
        Bhi + (size_t)bn * K, Blo + (size_t)bn * K
    };

    float acc[4][4][4];
    #pragma unroll
    for (int mi = 0; mi < 4; mi++)
        #pragma unroll
        for (int ni = 0; ni < 4; ni++)
            #pragma unroll
            for (int k = 0; k < 4; k++) acc[mi][ni][k] = 0.0f;

    auto stage_load = [&](int k0, int buf) {
        const uint32_t sb = sbase + buf * STAGE_B;
        #pragma unroll
        for (int it = 0; it < 8; it++) {
            const int flat = it * 256 + tid;
            const int m = flat >> 9;            // matrix 0..3
            const int rem = flat & 511;
            const int row = rem >> 2;           // 0..127
            const int seg = rem & 3;            // 16B segment
            cp_async16(sb + m * 8192 + swz(row, seg),
                       src[m] + (size_t)row * K + k0 + seg * 8);
        }
    };

    const int nch = K >> 5;
    stage_load(0, 0);
    CP_COMMIT();

    for (int c = 0; c < nch; c++) {
        if (c + 1 < nch) { stage_load((c + 1) << 5, (c + 1) & 1); CP_COMMIT(); CP_WAIT1(); }
        else             { CP_WAIT0(); }
        __syncthreads();

        const uint32_t sa = sbase + (c & 1) * STAGE_B;
        #pragma unroll
        for (int ks = 0; ks < 2; ks++) {
            const int seg = ks * 2 + (lane >> 4);
            uint32_t ah[4][4], al[4][4], bb[2][4];
            #pragma unroll
            for (int mi = 0; mi < 4; mi++) {
                const uint32_t addr = sa + swz(wm + mi * 16 + (lane & 15), seg);
                ldm_x4(ah[mi], addr);
                ldm_x4(al[mi], addr + 8192);
            }
            #pragma unroll
            for (int nb = 0; nb < 2; nb++)
                ldm_x4(bb[nb], sa + 16384 + swz(wn + nb * 16 + (lane & 15), seg));
            #pragma unroll
            for (int mi = 0; mi < 4; mi++)
                #pragma unroll
                for (int ni = 0; ni < 4; ni++) {
                    const uint32_t b0 = bb[ni >> 1][ni & 1];
                    const uint32_t b1 = bb[ni >> 1][(ni & 1) + 2];
                    mma16816(acc[mi][ni], ah[mi], b0, b1);
                    mma16816(acc[mi][ni], al[mi], b0, b1);
                }
            #pragma unroll
            for (int nb = 0; nb < 2; nb++)
                ldm_x4(bb[nb], sa + 24576 + swz(wn + nb * 16 + (lane & 15), seg));
            #pragma unroll
            for (int mi = 0; mi < 4; mi++)
                #pragma unroll
                for (int ni = 0; ni < 4; ni++) {
                    const uint32_t b0 = bb[ni >> 1][ni & 1];
                    const uint32_t b1 = bb[ni >> 1][(ni & 1) + 2];
                    mma16816(acc[mi][ni], ah[mi], b0, b1);
                }
        }
        __syncthreads();
    }

    // fused epilogue, direct from fragments
    const float sig = *invsig;
    int st = 0;
    if (STEP) st = *steps;
    const int quad = lane >> 2, tq = lane & 3;

    #pragma unroll
    for (int mi = 0; mi < 4; mi++) {
        #pragma unroll
        for (int ni = 0; ni < 4; ni++) {
            const int col = bn + wn + ni * 8 + tq * 2;
            const float b0 = bias[col], b1 = bias[col + 1];
            #pragma unroll
            for (int hr = 0; hr < 2; hr++) {
                const int row = bm + wm + mi * 16 + quad + hr * 8;
                const size_t idx = (size_t)row * N + col;
                float v0 = acc[mi][ni][hr * 2 + 0] * sig + b0;
                float v1 = acc[mi][ni][hr * 2 + 1] * sig + b1;
                if (STEP) {
                    if (t < st) {
                        const float2 xp = *(const float2*)(xproj + idx);
                        const float h0 = tanhf(xp.x + v0 * mod);
                        const float h1 = tanhf(xp.y + v1 * mod);
                        const __nv_bfloat16 h0h = __float2bfloat16(h0);
                        const __nv_bfloat16 h1h = __float2bfloat16(h1);
                        union { __nv_bfloat16 h[2]; uint32_t u; } ph, pl;
                        ph.h[0] = h0h; ph.h[1] = h1h;
                        pl.h[0] = __float2bfloat16(h0 - __bfloat162float(h0h));
                        pl.h[1] = __float2bfloat16(h1 - __bfloat162float(h1h));
                        *(uint32_t*)(Chi + idx) = ph.u;
                        *(uint32_t*)(Clo + idx) = pl.u;
                    } else {
                        *(uint32_t*)(Chi + idx) = *(const uint32_t*)(Hhi_old + idx);
                        *(uint32_t*)(Clo + idx) = *(const uint32_t*)(Hlo_old + idx);
                    }
                } else {
                    float2 o; o.x = v0; o.y = v1;
                    *(float2*)(Cf32 + idx) = o;
                }
            }
        }
    }
}

// ---------------------------------------------------------------------------
// launch
// ---------------------------------------------------------------------------
extern "C" void kernel_launch(void* const* d_in, const int* in_sizes, int n_in,
                              void* d_out, int out_size) {
    const float* x     = (const float*)d_in[0];
    const float* W_in  = (const float*)d_in[1];
    const float* b_in  = (const float*)d_in[2];
    const float* W_rec = (const float*)d_in[3];
    const float* b_rec = (const float*)d_in[4];
    const float* W_out = (const float*)d_in[5];
    const float* b_out = (const float*)d_in[6];
    const float* u_in  = (const float*)d_in[7];
    const float* u_rec = (const float*)d_in[8];
    const float* u_out = (const float*)d_in[9];
    const int*   steps = (const int*)d_in[10];

    const int H    = in_sizes[2];
    const int DIN  = in_sizes[1] / H;
    const int B    = in_sizes[0] / DIN;
    const int DOUT = in_sizes[6];

    __nv_bfloat16 *xhi, *xlo, *wih, *wil, *wrh, *wrl, *woh, *wol, *hhi, *hlo;
    float *xproj, *y, *v, *z, *invsig;
    cudaGetSymbolAddress((void**)&xhi, g_xhi);   cudaGetSymbolAddress((void**)&xlo, g_xlo);
    cudaGetSymbolAddress((void**)&wih, g_wih);   cudaGetSymbolAddress((void**)&wil, g_wil);
    cudaGetSymbolAddress((void**)&wrh, g_wrh);   cudaGetSymbolAddress((void**)&wrl, g_wrl);
    cudaGetSymbolAddress((void**)&woh, g_woh);   cudaGetSymbolAddress((void**)&wol, g_wol);
    cudaGetSymbolAddress((void**)&hhi, g_hhi);   cudaGetSymbolAddress((void**)&hlo, g_hlo);
    cudaGetSymbolAddress((void**)&xproj, g_xproj);
    cudaGetSymbolAddress((void**)&y, g_y); cudaGetSymbolAddress((void**)&v, g_v);
    cudaGetSymbolAddress((void**)&z, g_z); cudaGetSymbolAddress((void**)&invsig, g_invsig);

    __nv_bfloat16* hhi_b[2] = { hhi, hhi + (long)B_DIM * H_DIM };
    __nv_bfloat16* hlo_b[2] = { hlo, hlo + (long)B_DIM * H_DIM };

    cudaFuncSetAttribute(mma_gemm<false>, cudaFuncAttributeMaxDynamicSharedMemorySize, GEMM_SMEM);
    cudaFuncSetAttribute(mma_gemm<true>,  cudaFuncAttributeMaxDynamicSharedMemorySize, GEMM_SMEM);

    // spectral sigma
    auto spectral = [&](const float* W, const float* u, int R, int C, int idx) {
        zero_kernel<<<(C + 255) / 256, 256>>>(y, C);
        colmv_kernel<<<dim3((C + 127) / 128, 8), 128>>>(W, u, y, R, C);
        normalize_kernel<<<1, 256>>>(y, v, C);
        rowmv_kernel<<<(R + 7) / 8, 256>>>(W, v, z, R, C);
        sigma_kernel<<<1, 256>>>(z, invsig + idx, R);
    };
    spectral(W_in,  u_in,  H,    DIN, 0);
    spectral(W_rec, u_rec, H,    H,   1);
    spectral(W_out, u_out, DOUT, H,   2);

    // hi/lo splits
    {
        long n;
        n = (long)B * DIN;    split_kernel<<<(int)((n + 255) / 256), 256>>>(x, xhi, xlo, n);
        n = (long)H * DIN;    split_kernel<<<(int)((n + 255) / 256), 256>>>(W_in, wih, wil, n);
        n = (long)H * H;      split_kernel<<<(int)((n + 255) / 256), 256>>>(W_rec, wrh, wrl, n);
        n = (long)DOUT * H;   split_kernel<<<(int)((n + 255) / 256), 256>>>(W_out, woh, wol, n);
    }

    // x_proj = x @ (W_in/s)^T + b_in
    mma_gemm<false><<<dim3(H / 128, B / 128), 256, GEMM_SMEM>>>(
        xhi, xlo, wih, wil, b_in, invsig + 0, DIN, H,
        xproj, nullptr, nullptr, nullptr, nullptr, nullptr, 0.0f, 0, nullptr);

    // step 0
    {
        long total = (long)B * H;
        float mod0 = (float)(1.0 + 0.1 * sin(0.0));
        step0_kernel<<<(int)((total + 255) / 256), 256>>>(
            xproj, b_rec, hhi_b[0], hlo_b[0], total, H, mod0, steps);
    }

    // steps 1..29
    int cur = 0;
    for (int t = 1; t < NSTEPS; t++) {
        float mod = (float)(1.0 + 0.1 * sin(0.3 * (double)t));
        mma_gemm<true><<<dim3(H / 128, B / 128), 256, GEMM_SMEM>>>(
            hhi_b[cur], hlo_b[cur], wrh, wrl, b_rec, invsig + 1, H, H,
            nullptr, hhi_b[1 - cur], hlo_b[1 - cur],
            xproj, hhi_b[cur], hlo_b[cur], mod, t, steps);
        cur ^= 1;
    }

    // out = h @ (W_out/s)^T + b_out
    mma_gemm<false><<<dim3(DOUT / 128, B / 128), 256, GEMM_SMEM>>>(
        hhi_b[cur], hlo_b[cur], woh, wol, b_out, invsig + 2, H, DOUT,
        (float*)d_out, nullptr, nullptr, nullptr, nullptr, nullptr, 0.0f, 0, nullptr);
}

// round 4
// speedup vs baseline: 3.7868x; 1.4806x over previous
#include <cuda_runtime.h>
#include <cuda_fp16.h>
#include <math.h>
#include <stdint.h>

// ============================================================================
// HolomorphicEqProp — round 4: fp16 Ootomo-split GEMM (2 MMAs/tile for steps)
//   Weights: W = Whi + 2^-11 * Wlo'   (Wlo' = (W - fp16(W)) * 2^11, normal range)
//   D = A*Whi + (A*2^-11)*Wlo'        (fp32 accumulate; A plain fp16)
//   x_proj GEMM uses 3 MMAs (x also split) since its error feeds all steps.
// ============================================================================

#define H_DIM   1024
#define B_DIM   4096
#define NSTEPS  30

__device__ __forceinline__ uint32_t smem_u32(const void* p) {
    uint32_t a;
    asm("{ .reg .u64 t; cvta.to.shared.u64 t, %1; cvt.u32.u64 %0, t; }" : "=r"(a) : "l"(p));
    return a;
}
__device__ __forceinline__ void cp_async16(uint32_t saddr, const void* g) {
    asm volatile("cp.async.cg.shared.global [%0], [%1], 16;" :: "r"(saddr), "l"(g));
}
#define CP_COMMIT() asm volatile("cp.async.commit_group;" ::: "memory")
#define CP_WAIT(n)  asm volatile("cp.async.wait_group %0;" :: "n"(n) : "memory")

__device__ __forceinline__ void ldm_x4(uint32_t* r, uint32_t addr) {
    asm volatile("ldmatrix.sync.aligned.m8n8.x4.shared.b16 {%0,%1,%2,%3}, [%4];"
                 : "=r"(r[0]), "=r"(r[1]), "=r"(r[2]), "=r"(r[3]) : "r"(addr));
}
__device__ __forceinline__ void mma16816(float* c, const uint32_t* a, uint32_t b0, uint32_t b1) {
    asm volatile("mma.sync.aligned.m16n8k16.row.col.f32.f16.f16.f32 "
                 "{%0,%1,%2,%3}, {%4,%5,%6,%7}, {%8,%9}, {%0,%1,%2,%3};"
                 : "+f"(c[0]), "+f"(c[1]), "+f"(c[2]), "+f"(c[3])
                 : "r"(a[0]), "r"(a[1]), "r"(a[2]), "r"(a[3]), "r"(b0), "r"(b1));
}
// packed fp16x2 multiply by 2^-11 (exact exponent shift; subnormal loss harmless)
__device__ __forceinline__ uint32_t h2_scale_dn(uint32_t x) {
    uint32_t r;
    asm("mul.f16x2 %0, %1, %2;" : "=r"(r) : "r"(x), "r"(0x10001000u));
    return r;
}

// SW128-style placement: two 64B k-rows per 128B smem row, conflict-free for
// 16B cp.async stores and all ldmatrix phases (validated in round 3).
__device__ __forceinline__ uint32_t swz(int row, int seg) {
    return ((row >> 1) << 7) + (((((row & 1) << 2) | seg) ^ ((row >> 1) & 7)) << 4);
}

// ---------------------------------------------------------------------------
// static scratch
// ---------------------------------------------------------------------------
__device__ __half g_xhi[B_DIM * H_DIM], g_xlo[B_DIM * H_DIM];
__device__ __half g_wih[H_DIM * H_DIM], g_wil[H_DIM * H_DIM];
__device__ __half g_wrh[H_DIM * H_DIM], g_wrl[H_DIM * H_DIM];
__device__ __half g_woh[256 * H_DIM],  g_wol[256 * H_DIM];
__device__ float  g_xproj[B_DIM * H_DIM];
__device__ __half g_h[2][B_DIM * H_DIM];
__device__ float  g_y[H_DIM], g_v[H_DIM], g_z[H_DIM], g_invsig[3];

// ---------------------------------------------------------------------------
// spectral norm (unchanged, tiny)
// ---------------------------------------------------------------------------
__device__ __forceinline__ float block_reduce_sum(float v) {
    __shared__ float sh[32];
    int lane = threadIdx.x & 31, w = threadIdx.x >> 5;
    #pragma unroll
    for (int o = 16; o; o >>= 1) v += __shfl_xor_sync(0xffffffffu, v, o);
    if (!lane) sh[w] = v;
    __syncthreads();
    int nw = blockDim.x >> 5;
    v = (threadIdx.x < nw) ? sh[threadIdx.x] : 0.0f;
    if (w == 0) {
        #pragma unroll
        for (int o = 16; o; o >>= 1) v += __shfl_xor_sync(0xffffffffu, v, o);
        if (!lane) sh[0] = v;
    }
    __syncthreads();
    return sh[0];
}

__global__ void zero_kernel(float* p, int n) {
    int i = blockIdx.x * blockDim.x + threadIdx.x;
    if (i < n) p[i] = 0.0f;
}
__global__ void colmv_kernel(const float* __restrict__ W, const float* __restrict__ u,
                             float* __restrict__ y, int R, int C) {
    int c = blockIdx.x * blockDim.x + threadIdx.x;
    if (c >= C) return;
    int per = R / gridDim.y;
    int r0 = blockIdx.y * per;
    int r1 = (blockIdx.y == gridDim.y - 1) ? R : r0 + per;
    float acc = 0.0f;
    for (int r = r0; r < r1; r++) acc += W[(long)r * C + c] * u[r];
    atomicAdd(&y[c], acc);
}
__global__ void normalize_kernel(const float* __restrict__ y, float* __restrict__ v, int n) {
    float ss = 0.0f;
    for (int i = threadIdx.x; i < n; i += blockDim.x) { float t = y[i]; ss += t * t; }
    float tot = block_reduce_sum(ss);
    float scale = 1.0f / (sqrtf(tot) + 1e-12f);
    for (int i = threadIdx.x; i < n; i += blockDim.x) v[i] = y[i] * scale;
}
__global__ void rowmv_kernel(const float* __restrict__ W, const float* __restrict__ v,
                             float* __restrict__ z, int R, int C) {
    int warp = (blockIdx.x * blockDim.x + threadIdx.x) >> 5;
    int lane = threadIdx.x & 31;
    if (warp >= R) return;
    float acc = 0.0f;
    for (int c = lane; c < C; c += 32) acc += W[(long)warp * C + c] * v[c];
    #pragma unroll
    for (int o = 16; o; o >>= 1) acc += __shfl_xor_sync(0xffffffffu, acc, o);
    if (!lane) z[warp] = acc;
}
__global__ void sigma_kernel(const float* __restrict__ z, float* __restrict__ invsig, int n) {
    float ss = 0.0f;
    for (int i = threadIdx.x; i < n; i += blockDim.x) { float t = z[i]; ss += t * t; }
    float tot = block_reduce_sum(ss);
    if (threadIdx.x == 0) {
        float nz = sqrtf(tot);
        invsig[0] = (nz + 1e-12f) / tot;
    }
}

// ---------------------------------------------------------------------------
// fp32 -> fp16 Ootomo split: hi = fp16(f), lo = fp16((f - hi) * 2^11)
// ---------------------------------------------------------------------------
__global__ void splitw_kernel(const float* __restrict__ s, __half* __restrict__ hi,
                              __half* __restrict__ lo, long n) {
    long i = (long)blockIdx.x * blockDim.x + threadIdx.x;
    if (i >= n) return;
    float f = s[i];
    __half h = __float2half_rn(f);
    hi[i] = h;
    lo[i] = __float2half_rn((f - __half2float(h)) * 2048.0f);
}

// step 0 (h0 = 0): h1 = tanh(xproj + b_rec*mod), plain fp16
__global__ void step0_kernel(const float* __restrict__ xproj, const float* __restrict__ brec,
                             __half* __restrict__ h, long total, int H, float mod,
                             const int* __restrict__ steps) {
    long i = (long)blockIdx.x * blockDim.x + threadIdx.x;
    if (i >= total) return;
    float val = (0 < *steps) ? tanhf(xproj[i] + brec[i % H] * mod) : 0.0f;
    h[i] = __float2half_rn(val);
}

// ---------------------------------------------------------------------------
// fp16 split GEMM: C[128x128 tile] = A[M,K] @ (Bhi + 2^-11 Blo')[N,K]^T
//   ATERMS==1: 2 MMAs per frag (A·Bhi + scaled(A)·Blo')
//   ATERMS==2: +1 MMA (scaled(A2)·Bhi) — used for x_proj only
//   8 warps, warp tile 64x32, K chunks of 32, cp.async multi-stage pipeline.
// ---------------------------------------------------------------------------
template <int ATERMS, bool STEP>
__global__ __launch_bounds__(256, 2)
void mma_gemm(const __half* __restrict__ A1, const __half* __restrict__ A2,
              const __half* __restrict__ B1, const __half* __restrict__ B2,
              const float* __restrict__ bias, const float* __restrict__ invsig,
              int K, int N,
              float* __restrict__ Cf32, __half* __restrict__ Ch,
              const float* __restrict__ xproj, const __half* __restrict__ Hold,
              float mod, int t, const int* __restrict__ steps) {
    constexpr int NM = ATERMS + 2;            // matrices per stage
    constexpr int STAGE_B = NM * 8192;
    constexpr int STAGES = (ATERMS == 2) ? 2 : 3;

    extern __shared__ char sm[];
    const uint32_t sbase = smem_u32(sm);

    const int tid  = threadIdx.x;
    const int wid  = tid >> 5;
    const int lane = tid & 31;
    const int bm   = blockIdx.y * 128;
    const int bn   = blockIdx.x * 128;
    const int wm   = (wid >> 2) * 64;
    const int wn   = (wid & 3) * 32;

    const __half* src[4];
    src[0] = A1 + (size_t)bm * K;
    src[1] = B1 + (size_t)bn * K;
    src[2] = B2 + (size_t)bn * K;
    src[3] = (ATERMS == 2) ? (A2 + (size_t)bm * K) : A1;

    float acc[4][4][4];
    #pragma unroll
    for (int mi = 0; mi < 4; mi++)
        #pragma unroll
        for (int ni = 0; ni < 4; ni++)
            #pragma unroll
            for (int k = 0; k < 4; k++) acc[mi][ni][k] = 0.0f;

    auto stage_load = [&](int chunk, int buf) {
        const uint32_t sb = sbase + buf * STAGE_B;
        const int k0 = chunk << 5;
        #pragma unroll
        for (int it = 0; it < 2 * NM; it++) {
            const int flat = it * 256 + tid;
            const int m = flat >> 9;
            const int rem = flat & 511;
            const int row = rem >> 2;
            const int seg = rem & 3;
            cp_async16(sb + m * 8192 + swz(row, seg),
                       src[m] + (size_t)row * K + k0 + seg * 8);
        }
    };

    const int nch = K >> 5;
    stage_load(0, 0);
    CP_COMMIT();
    if (STAGES == 3) { stage_load(1, 1); CP_COMMIT(); }

    for (int c = 0; c < nch; c++) {
        if (c + STAGES - 1 < nch) {
            stage_load(c + STAGES - 1, (c + STAGES - 1) % STAGES);
            CP_COMMIT();
            if (STAGES == 3) CP_WAIT(2); else CP_WAIT(1);
        } else if (STAGES == 3 && c + 1 < nch) {
            CP_WAIT(1);
        } else {
            CP_WAIT(0);
        }
        __syncthreads();

        const uint32_t sa = sbase + (c % STAGES) * STAGE_B;
        #pragma unroll
        for (int ks = 0; ks < 2; ks++) {
            const int seg = ks * 2 + (lane >> 4);
            uint32_t af[4][4], b1[2][4], b2[2][4];
            #pragma unroll
            for (int mi = 0; mi < 4; mi++)
                ldm_x4(af[mi], sa + swz(wm + mi * 16 + (lane & 15), seg));
            #pragma unroll
            for (int nb = 0; nb < 2; nb++) {
                ldm_x4(b1[nb], sa + 8192  + swz(wn + nb * 16 + (lane & 15), seg));
                ldm_x4(b2[nb], sa + 16384 + swz(wn + nb * 16 + (lane & 15), seg));
            }
            // main term: A * Bhi
            #pragma unroll
            for (int mi = 0; mi < 4; mi++)
                #pragma unroll
                for (int ni = 0; ni < 4; ni++)
                    mma16816(acc[mi][ni], af[mi],
                             b1[ni >> 1][ni & 1], b1[ni >> 1][(ni & 1) + 2]);
            // correction: (A * 2^-11) * Blo'
            #pragma unroll
            for (int mi = 0; mi < 4; mi++)
                #pragma unroll
                for (int r = 0; r < 4; r++) af[mi][r] = h2_scale_dn(af[mi][r]);
            #pragma unroll
            for (int mi = 0; mi < 4; mi++)
                #pragma unroll
                for (int ni = 0; ni < 4; ni++)
                    mma16816(acc[mi][ni], af[mi],
                             b2[ni >> 1][ni & 1], b2[ni >> 1][(ni & 1) + 2]);
            if (ATERMS == 2) {
                // A-residual term: (A2' * 2^-11) * Bhi
                #pragma unroll
                for (int mi = 0; mi < 4; mi++) {
                    ldm_x4(af[mi], sa + 24576 + swz(wm + mi * 16 + (lane & 15), seg));
                    #pragma unroll
                    for (int r = 0; r < 4; r++) af[mi][r] = h2_scale_dn(af[mi][r]);
                }
                #pragma unroll
                for (int mi = 0; mi < 4; mi++)
                    #pragma unroll
                    for (int ni = 0; ni < 4; ni++)
                        mma16816(acc[mi][ni], af[mi],
                                 b1[ni >> 1][ni & 1], b1[ni >> 1][(ni & 1) + 2]);
            }
        }
        __syncthreads();
    }

    // fused epilogue from fragments
    const float sig = *invsig;
    int st = 0;
    if (STEP) st = *steps;
    const int quad = lane >> 2, tq = lane & 3;

    #pragma unroll
    for (int mi = 0; mi < 4; mi++) {
        #pragma unroll
        for (int ni = 0; ni < 4; ni++) {
            const int col = bn + wn + ni * 8 + tq * 2;
            const float b0 = bias[col], b1v = bias[col + 1];
            #pragma unroll
            for (int hr = 0; hr < 2; hr++) {
                const int row = bm + wm + mi * 16 + quad + hr * 8;
                const size_t idx = (size_t)row * N + col;
                float v0 = acc[mi][ni][hr * 2 + 0] * sig + b0;
                float v1 = acc[mi][ni][hr * 2 + 1] * sig + b1v;
                if (STEP) {
                    if (t < st) {
                        const float2 xp = *(const float2*)(xproj + idx);
                        const float h0 = tanhf(xp.x + v0 * mod);
                        const float h1 = tanhf(xp.y + v1 * mod);
                        union { __half h[2]; uint32_t u; } ph;
                        ph.h[0] = __float2half_rn(h0);
                        ph.h[1] = __float2half_rn(h1);
                        *(uint32_t*)(Ch + idx) = ph.u;
                    } else {
                        *(uint32_t*)(Ch + idx) = *(const uint32_t*)(Hold + idx);
                    }
                } else {
                    float2 o; o.x = v0; o.y = v1;
                    *(float2*)(Cf32 + idx) = o;
                }
            }
        }
    }
}

// ---------------------------------------------------------------------------
// launch
// ---------------------------------------------------------------------------
extern "C" void kernel_launch(void* const* d_in, const int* in_sizes, int n_in,
                              void* d_out, int out_size) {
    const float* x     = (const float*)d_in[0];
    const float* W_in  = (const float*)d_in[1];
    const float* b_in  = (const float*)d_in[2];
    const float* W_rec = (const float*)d_in[3];
    const float* b_rec = (const float*)d_in[4];
    const float* W_out = (const float*)d_in[5];
    const float* b_out = (const float*)d_in[6];
    const float* u_in  = (const float*)d_in[7];
    const float* u_rec = (const float*)d_in[8];
    const float* u_out = (const float*)d_in[9];
    const int*   steps = (const int*)d_in[10];

    const int H    = in_sizes[2];
    const int DIN  = in_sizes[1] / H;
    const int B    = in_sizes[0] / DIN;
    const int DOUT = in_sizes[6];

    __half *xhi, *xlo, *wih, *wil, *wrh, *wrl, *woh, *wol, *hbuf0;
    float *xproj, *y, *v, *z, *invsig;
    cudaGetSymbolAddress((void**)&xhi, g_xhi);   cudaGetSymbolAddress((void**)&xlo, g_xlo);
    cudaGetSymbolAddress((void**)&wih, g_wih);   cudaGetSymbolAddress((void**)&wil, g_wil);
    cudaGetSymbolAddress((void**)&wrh, g_wrh);   cudaGetSymbolAddress((void**)&wrl, g_wrl);
    cudaGetSymbolAddress((void**)&woh, g_woh);   cudaGetSymbolAddress((void**)&wol, g_wol);
    cudaGetSymbolAddress((void**)&hbuf0, g_h);
    cudaGetSymbolAddress((void**)&xproj, g_xproj);
    cudaGetSymbolAddress((void**)&y, g_y); cudaGetSymbolAddress((void**)&v, g_v);
    cudaGetSymbolAddress((void**)&z, g_z); cudaGetSymbolAddress((void**)&invsig, g_invsig);

    __half* hb[2] = { hbuf0, hbuf0 + (long)B_DIM * H_DIM };

    constexpr int SMEM_A1 = 3 * 3 * 8192;   // 3 matrices, 3 stages = 72KB
    constexpr int SMEM_A2 = 2 * 4 * 8192;   // 4 matrices, 2 stages = 64KB
    cudaFuncSetAttribute(mma_gemm<1, true>,  cudaFuncAttributeMaxDynamicSharedMemorySize, SMEM_A1);
    cudaFuncSetAttribute(mma_gemm<1, false>, cudaFuncAttributeMaxDynamicSharedMemorySize, SMEM_A1);
    cudaFuncSetAttribute(mma_gemm<2, false>, cudaFuncAttributeMaxDynamicSharedMemorySize, SMEM_A2);

    // spectral sigma
    auto spectral = [&](const float* W, const float* u, int R, int C, int idx) {
        zero_kernel<<<(C + 255) / 256, 256>>>(y, C);
        colmv_kernel<<<dim3((C + 127) / 128, 8), 128>>>(W, u, y, R, C);
        normalize_kernel<<<1, 256>>>(y, v, C);
        rowmv_kernel<<<(R + 7) / 8, 256>>>(W, v, z, R, C);
        sigma_kernel<<<1, 256>>>(z, invsig + idx, R);
    };
    spectral(W_in,  u_in,  H,    DIN, 0);
    spectral(W_rec, u_rec, H,    H,   1);
    spectral(W_out, u_out, DOUT, H,   2);

    // Ootomo splits
    {
        long n;
        n = (long)B * DIN;  splitw_kernel<<<(int)((n + 255) / 256), 256>>>(x, xhi, xlo, n);
        n = (long)H * DIN;  splitw_kernel<<<(int)((n + 255) / 256), 256>>>(W_in, wih, wil, n);
        n = (long)H * H;    splitw_kernel<<<(int)((n + 255) / 256), 256>>>(W_rec, wrh, wrl, n);
        n = (long)DOUT * H; splitw_kernel<<<(int)((n + 255) / 256), 256>>>(W_out, woh, wol, n);
    }

    // x_proj = x @ (W_in/s)^T + b_in   (3-MMA, high accuracy)
    mma_gemm<2, false><<<dim3(H / 128, B / 128), 256, SMEM_A2>>>(
        xhi, xlo, wih, wil, b_in, invsig + 0, DIN, H,
        xproj, nullptr, nullptr, nullptr, 0.0f, 0, nullptr);

    // step 0
    {
        long total = (long)B * H;
        float mod0 = (float)(1.0 + 0.1 * sin(0.0));
        step0_kernel<<<(int)((total + 255) / 256), 256>>>(
            xproj, b_rec, hb[0], total, H, mod0, steps);
    }

    // steps 1..29 (2-MMA)
    int cur = 0;
    for (int t = 1; t < NSTEPS; t++) {
        float mod = (float)(1.0 + 0.1 * sin(0.3 * (double)t));
        mma_gemm<1, true><<<dim3(H / 128, B / 128), 256, SMEM_A1>>>(
            hb[cur], nullptr, wrh, wrl, b_rec, invsig + 1, H, H,
            nullptr, hb[1 - cur], xproj, hb[cur], mod, t, steps);
        cur ^= 1;
    }

    // out = h @ (W_out/s)^T + b_out (2-MMA)
    mma_gemm<1, false><<<dim3(DOUT / 128, B / 128), 256, SMEM_A1>>>(
        hb[cur], nullptr, woh, wol, b_out, invsig + 2, H, DOUT,
        (float*)d_out, nullptr, nullptr, nullptr, 0.0f, 0, nullptr);
}

// round 5
// speedup vs baseline: 6.4025x; 1.6907x over previous
#include <cuda_runtime.h>
#include <cuda_fp16.h>
#include <math.h>
#include <stdint.h>

// ============================================================================
// HolomorphicEqProp — round 5: steps use plain-fp16 weights (1 MMA per frag)
//   step GEMM : D = A * fp16(W)           (fp32 accum; error budget verified)
//   out GEMM  : D = A*Whi + (A*2^-11)*Wlo'            (2-term, weight-exact)
//   xproj GEMM: D = Ahi*Whi + (Ahi*2^-11)*Wlo' + (Alo'*2^-11)*Whi  (3-term)
// ============================================================================

#define H_DIM   1024
#define B_DIM   4096
#define NSTEPS  30

__device__ __forceinline__ uint32_t smem_u32(const void* p) {
    uint32_t a;
    asm("{ .reg .u64 t; cvta.to.shared.u64 t, %1; cvt.u32.u64 %0, t; }" : "=r"(a) : "l"(p));
    return a;
}
__device__ __forceinline__ void cp_async16(uint32_t saddr, const void* g) {
    asm volatile("cp.async.cg.shared.global [%0], [%1], 16;" :: "r"(saddr), "l"(g));
}
#define CP_COMMIT() asm volatile("cp.async.commit_group;" ::: "memory")
#define CP_WAIT(n)  asm volatile("cp.async.wait_group %0;" :: "n"(n) : "memory")

__device__ __forceinline__ void ldm_x4(uint32_t* r, uint32_t addr) {
    asm volatile("ldmatrix.sync.aligned.m8n8.x4.shared.b16 {%0,%1,%2,%3}, [%4];"
                 : "=r"(r[0]), "=r"(r[1]), "=r"(r[2]), "=r"(r[3]) : "r"(addr));
}
__device__ __forceinline__ void mma16816(float* c, const uint32_t* a, uint32_t b0, uint32_t b1) {
    asm volatile("mma.sync.aligned.m16n8k16.row.col.f32.f16.f16.f32 "
                 "{%0,%1,%2,%3}, {%4,%5,%6,%7}, {%8,%9}, {%0,%1,%2,%3};"
                 : "+f"(c[0]), "+f"(c[1]), "+f"(c[2]), "+f"(c[3])
                 : "r"(a[0]), "r"(a[1]), "r"(a[2]), "r"(a[3]), "r"(b0), "r"(b1));
}
__device__ __forceinline__ uint32_t h2_scale_dn(uint32_t x) {   // * 2^-11 packed
    uint32_t r;
    asm("mul.f16x2 %0, %1, %2;" : "=r"(r) : "r"(x), "r"(0x10001000u));
    return r;
}

// standard SW128 swizzle on full 128-byte rows (k-chunk = 64 fp16)
__device__ __forceinline__ uint32_t swz(int row, int seg) {
    uint32_t o = ((uint32_t)row << 7) | ((uint32_t)seg << 4);
    return o ^ ((o >> 3) & 0x70);
}

// ---------------------------------------------------------------------------
// static scratch
// ---------------------------------------------------------------------------
__device__ __half g_xhi[B_DIM * H_DIM], g_xlo[B_DIM * H_DIM];
__device__ __half g_wih[H_DIM * H_DIM], g_wil[H_DIM * H_DIM];
__device__ __half g_wrh[H_DIM * H_DIM], g_wrl[H_DIM * H_DIM];
__device__ __half g_woh[256 * H_DIM],  g_wol[256 * H_DIM];
__device__ float  g_xproj[B_DIM * H_DIM];
__device__ __half g_h[2][B_DIM * H_DIM];
__device__ float  g_y[H_DIM], g_v[H_DIM], g_z[H_DIM], g_invsig[3];

// ---------------------------------------------------------------------------
// spectral norm (tiny)
// ---------------------------------------------------------------------------
__device__ __forceinline__ float block_reduce_sum(float v) {
    __shared__ float sh[32];
    int lane = threadIdx.x & 31, w = threadIdx.x >> 5;
    #pragma unroll
    for (int o = 16; o; o >>= 1) v += __shfl_xor_sync(0xffffffffu, v, o);
    if (!lane) sh[w] = v;
    __syncthreads();
    int nw = blockDim.x >> 5;
    v = (threadIdx.x < nw) ? sh[threadIdx.x] : 0.0f;
    if (w == 0) {
        #pragma unroll
        for (int o = 16; o; o >>= 1) v += __shfl_xor_sync(0xffffffffu, v, o);
        if (!lane) sh[0] = v;
    }
    __syncthreads();
    return sh[0];
}

__global__ void zero_kernel(float* p, int n) {
    int i = blockIdx.x * blockDim.x + threadIdx.x;
    if (i < n) p[i] = 0.0f;
}
__global__ void colmv_kernel(const float* __restrict__ W, const float* __restrict__ u,
                             float* __restrict__ y, int R, int C) {
    int c = blockIdx.x * blockDim.x + threadIdx.x;
    if (c >= C) return;
    int per = R / gridDim.y;
    int r0 = blockIdx.y * per;
    int r1 = (blockIdx.y == gridDim.y - 1) ? R : r0 + per;
    float acc = 0.0f;
    for (int r = r0; r < r1; r++) acc += W[(long)r * C + c] * u[r];
    atomicAdd(&y[c], acc);
}
__global__ void normalize_kernel(const float* __restrict__ y, float* __restrict__ v, int n) {
    float ss = 0.0f;
    for (int i = threadIdx.x; i < n; i += blockDim.x) { float t = y[i]; ss += t * t; }
    float tot = block_reduce_sum(ss);
    float scale = 1.0f / (sqrtf(tot) + 1e-12f);
    for (int i = threadIdx.x; i < n; i += blockDim.x) v[i] = y[i] * scale;
}
__global__ void rowmv_kernel(const float* __restrict__ W, const float* __restrict__ v,
                             float* __restrict__ z, int R, int C) {
    int warp = (blockIdx.x * blockDim.x + threadIdx.x) >> 5;
    int lane = threadIdx.x & 31;
    if (warp >= R) return;
    float acc = 0.0f;
    for (int c = lane; c < C; c += 32) acc += W[(long)warp * C + c] * v[c];
    #pragma unroll
    for (int o = 16; o; o >>= 1) acc += __shfl_xor_sync(0xffffffffu, acc, o);
    if (!lane) z[warp] = acc;
}
__global__ void sigma_kernel(const float* __restrict__ z, float* __restrict__ invsig, int n) {
    float ss = 0.0f;
    for (int i = threadIdx.x; i < n; i += blockDim.x) { float t = z[i]; ss += t * t; }
    float tot = block_reduce_sum(ss);
    if (threadIdx.x == 0) {
        float nz = sqrtf(tot);
        invsig[0] = (nz + 1e-12f) / tot;
    }
}

// fp32 -> fp16 Ootomo split
__global__ void splitw_kernel(const float* __restrict__ s, __half* __restrict__ hi,
                              __half* __restrict__ lo, long n) {
    long i = (long)blockIdx.x * blockDim.x + threadIdx.x;
    if (i >= n) return;
    float f = s[i];
    __half h = __float2half_rn(f);
    hi[i] = h;
    lo[i] = __float2half_rn((f - __half2float(h)) * 2048.0f);
}

// step 0 (h0 = 0): h1 = tanh(xproj + b_rec*mod)
__global__ void step0_kernel(const float* __restrict__ xproj, const float* __restrict__ brec,
                             __half* __restrict__ h, long total, int H, float mod,
                             const int* __restrict__ steps) {
    long i = (long)blockIdx.x * blockDim.x + threadIdx.x;
    if (i >= total) return;
    float val = (0 < *steps) ? tanhf(xproj[i] + brec[i % H] * mod) : 0.0f;
    h[i] = __float2half_rn(val);
}

// ---------------------------------------------------------------------------
// fp16 GEMM: C[128x128 tile] = A[M,K] @ B[N,K]^T + fused epilogue
//   K chunks of 64 (one SW128 row), cp.async pipeline.
//   ATERMS/BTERMS select correction terms (see header).
// ---------------------------------------------------------------------------
template <int ATERMS, int BTERMS, bool STEP>
__global__ __launch_bounds__(256, 2)
void mma_gemm(const __half* __restrict__ A1, const __half* __restrict__ A2,
              const __half* __restrict__ B1, const __half* __restrict__ B2,
              const float* __restrict__ bias, const float* __restrict__ invsig,
              int K, int N,
              float* __restrict__ Cf32, __half* __restrict__ Ch,
              const float* __restrict__ xproj, const __half* __restrict__ Hold,
              float mod, int t, const int* __restrict__ steps) {
    constexpr int NM = ATERMS + BTERMS;        // matrices per stage
    constexpr int MAT_B = 16384;               // 128 rows x 128 bytes
    constexpr int STAGE_B = NM * MAT_B;
    constexpr int STAGES = (NM == 2) ? 3 : 2;

    extern __shared__ char sm[];
    const uint32_t sbase = smem_u32(sm);

    const int tid  = threadIdx.x;
    const int wid  = tid >> 5;
    const int lane = tid & 31;
    const int bm   = blockIdx.y * 128;
    const int bn   = blockIdx.x * 128;
    const int wm   = (wid >> 2) * 64;
    const int wn   = (wid & 3) * 32;

    // slot order: A1, B1, [B2], [A2]
    const __half* src[4];
    src[0] = A1 + (size_t)bm * K;
    src[1] = B1 + (size_t)bn * K;
    src[2] = (BTERMS == 2) ? (B2 + (size_t)bn * K)
                           : ((ATERMS == 2) ? (A2 + (size_t)bm * K) : src[0]);
    src[3] = (NM == 4) ? (A2 + (size_t)bm * K) : src[0];
    const uint32_t A2_OFF = (BTERMS == 2) ? 3 * MAT_B : 2 * MAT_B;

    float acc[4][4][4];
    #pragma unroll
    for (int mi = 0; mi < 4; mi++)
        #pragma unroll
        for (int ni = 0; ni < 4; ni++)
            #pragma unroll
            for (int k = 0; k < 4; k++) acc[mi][ni][k] = 0.0f;

    auto stage_load = [&](int chunk, int buf) {
        const uint32_t sb = sbase + buf * STAGE_B;
        const int k0 = chunk << 6;
        #pragma unroll
        for (int it = 0; it < 4 * NM; it++) {
            const int flat = it * 256 + tid;
            const int m = flat >> 10;
            const int rem = flat & 1023;
            const int row = rem >> 3;
            const int seg = rem & 7;
            cp_async16(sb + m * MAT_B + swz(row, seg),
                       src[m] + (size_t)row * K + k0 + seg * 8);
        }
    };

    const int nch = K >> 6;
    stage_load(0, 0);
    CP_COMMIT();
    if (STAGES == 3) { stage_load(1, 1); CP_COMMIT(); }

    for (int c = 0; c < nch; c++) {
        if (c + STAGES - 1 < nch) {
            stage_load(c + STAGES - 1, (c + STAGES - 1) % STAGES);
            CP_COMMIT();
            if (STAGES == 3) CP_WAIT(2); else CP_WAIT(1);
        } else if (STAGES == 3 && c + 1 < nch) {
            CP_WAIT(1);
        } else {
            CP_WAIT(0);
        }
        __syncthreads();

        const uint32_t sa = sbase + (c % STAGES) * STAGE_B;
        #pragma unroll
        for (int ks = 0; ks < 4; ks++) {
            const int seg = ks * 2 + (lane >> 4);
            uint32_t af[4][4], b1[2][4];
            #pragma unroll
            for (int mi = 0; mi < 4; mi++)
                ldm_x4(af[mi], sa + swz(wm + mi * 16 + (lane & 15), seg));
            #pragma unroll
            for (int nb = 0; nb < 2; nb++)
                ldm_x4(b1[nb], sa + MAT_B + swz(wn + nb * 16 + (lane & 15), seg));
            // main: A * Bhi
            #pragma unroll
            for (int mi = 0; mi < 4; mi++)
                #pragma unroll
                for (int ni = 0; ni < 4; ni++)
                    mma16816(acc[mi][ni], af[mi],
                             b1[ni >> 1][ni & 1], b1[ni >> 1][(ni & 1) + 2]);
            if (BTERMS == 2) {
                // correction: (A * 2^-11) * Blo'
                uint32_t b2f[2][4];
                #pragma unroll
                for (int nb = 0; nb < 2; nb++)
                    ldm_x4(b2f[nb], sa + 2 * MAT_B + swz(wn + nb * 16 + (lane & 15), seg));
                #pragma unroll
                for (int mi = 0; mi < 4; mi++)
                    #pragma unroll
                    for (int r = 0; r < 4; r++) af[mi][r] = h2_scale_dn(af[mi][r]);
                #pragma unroll
                for (int mi = 0; mi < 4; mi++)
                    #pragma unroll
                    for (int ni = 0; ni < 4; ni++)
                        mma16816(acc[mi][ni], af[mi],
                                 b2f[ni >> 1][ni & 1], b2f[ni >> 1][(ni & 1) + 2]);
            }
            if (ATERMS == 2) {
                // A residual: (Alo' * 2^-11) * Bhi
                #pragma unroll
                for (int mi = 0; mi < 4; mi++) {
                    ldm_x4(af[mi], sa + A2_OFF + swz(wm + mi * 16 + (lane & 15), seg));
                    #pragma unroll
                    for (int r = 0; r < 4; r++) af[mi][r] = h2_scale_dn(af[mi][r]);
                }
                #pragma unroll
                for (int mi = 0; mi < 4; mi++)
                    #pragma unroll
                    for (int ni = 0; ni < 4; ni++)
                        mma16816(acc[mi][ni], af[mi],
                                 b1[ni >> 1][ni & 1], b1[ni >> 1][(ni & 1) + 2]);
            }
        }
        __syncthreads();
    }

    // fused epilogue
    const float sig = *invsig;
    int st = 0;
    if (STEP) st = *steps;
    const int quad = lane >> 2, tq = lane & 3;

    #pragma unroll
    for (int mi = 0; mi < 4; mi++) {
        #pragma unroll
        for (int ni = 0; ni < 4; ni++) {
            const int col = bn + wn + ni * 8 + tq * 2;
            const float b0 = bias[col], b1v = bias[col + 1];
            #pragma unroll
            for (int hr = 0; hr < 2; hr++) {
                const int row = bm + wm + mi * 16 + quad + hr * 8;
                const size_t idx = (size_t)row * N + col;
                float v0 = acc[mi][ni][hr * 2 + 0] * sig + b0;
                float v1 = acc[mi][ni][hr * 2 + 1] * sig + b1v;
                if (STEP) {
                    if (t < st) {
                        const float2 xp = *(const float2*)(xproj + idx);
                        const float h0 = tanhf(xp.x + v0 * mod);
                        const float h1 = tanhf(xp.y + v1 * mod);
                        union { __half h[2]; uint32_t u; } ph;
                        ph.h[0] = __float2half_rn(h0);
                        ph.h[1] = __float2half_rn(h1);
                        *(uint32_t*)(Ch + idx) = ph.u;
                    } else {
                        *(uint32_t*)(Ch + idx) = *(const uint32_t*)(Hold + idx);
                    }
                } else {
                    float2 o; o.x = v0; o.y = v1;
                    *(float2*)(Cf32 + idx) = o;
                }
            }
        }
    }
}

// ---------------------------------------------------------------------------
// launch
// ---------------------------------------------------------------------------
extern "C" void kernel_launch(void* const* d_in, const int* in_sizes, int n_in,
                              void* d_out, int out_size) {
    const float* x     = (const float*)d_in[0];
    const float* W_in  = (const float*)d_in[1];
    const float* b_in  = (const float*)d_in[2];
    const float* W_rec = (const float*)d_in[3];
    const float* b_rec = (const float*)d_in[4];
    const float* W_out = (const float*)d_in[5];
    const float* b_out = (const float*)d_in[6];
    const float* u_in  = (const float*)d_in[7];
    const float* u_rec = (const float*)d_in[8];
    const float* u_out = (const float*)d_in[9];
    const int*   steps = (const int*)d_in[10];

    const int H    = in_sizes[2];
    const int DIN  = in_sizes[1] / H;
    const int B    = in_sizes[0] / DIN;
    const int DOUT = in_sizes[6];

    __half *xhi, *xlo, *wih, *wil, *wrh, *wrl, *woh, *wol, *hbuf0;
    float *xproj, *y, *v, *z, *invsig;
    cudaGetSymbolAddress((void**)&xhi, g_xhi);   cudaGetSymbolAddress((void**)&xlo, g_xlo);
    cudaGetSymbolAddress((void**)&wih, g_wih);   cudaGetSymbolAddress((void**)&wil, g_wil);
    cudaGetSymbolAddress((void**)&wrh, g_wrh);   cudaGetSymbolAddress((void**)&wrl, g_wrl);
    cudaGetSymbolAddress((void**)&woh, g_woh);   cudaGetSymbolAddress((void**)&wol, g_wol);
    cudaGetSymbolAddress((void**)&hbuf0, g_h);
    cudaGetSymbolAddress((void**)&xproj, g_xproj);
    cudaGetSymbolAddress((void**)&y, g_y); cudaGetSymbolAddress((void**)&v, g_v);
    cudaGetSymbolAddress((void**)&z, g_z); cudaGetSymbolAddress((void**)&invsig, g_invsig);

    __half* hb[2] = { hbuf0, hbuf0 + (long)B_DIM * H_DIM };

    constexpr int SMEM_STEP  = 3 * 2 * 16384;   // 3 stages x 2 mats = 96KB
    constexpr int SMEM_OUT   = 2 * 3 * 16384;   // 2 stages x 3 mats = 96KB
    constexpr int SMEM_XPROJ = 2 * 4 * 16384;   // 2 stages x 4 mats = 128KB
    cudaFuncSetAttribute(mma_gemm<1, 1, true>,  cudaFuncAttributeMaxDynamicSharedMemorySize, SMEM_STEP);
    cudaFuncSetAttribute(mma_gemm<1, 2, false>, cudaFuncAttributeMaxDynamicSharedMemorySize, SMEM_OUT);
    cudaFuncSetAttribute(mma_gemm<2, 2, false>, cudaFuncAttributeMaxDynamicSharedMemorySize, SMEM_XPROJ);

    // spectral sigma
    auto spectral = [&](const float* W, const float* u, int R, int C, int idx) {
        zero_kernel<<<(C + 255) / 256, 256>>>(y, C);
        colmv_kernel<<<dim3((C + 127) / 128, 8), 128>>>(W, u, y, R, C);
        normalize_kernel<<<1, 256>>>(y, v, C);
        rowmv_kernel<<<(R + 7) / 8, 256>>>(W, v, z, R, C);
        sigma_kernel<<<1, 256>>>(z, invsig + idx, R);
    };
    spectral(W_in,  u_in,  H,    DIN, 0);
    spectral(W_rec, u_rec, H,    H,   1);
    spectral(W_out, u_out, DOUT, H,   2);

    // splits
    {
        long n;
        n = (long)B * DIN;  splitw_kernel<<<(int)((n + 255) / 256), 256>>>(x, xhi, xlo, n);
        n = (long)H * DIN;  splitw_kernel<<<(int)((n + 255) / 256), 256>>>(W_in, wih, wil, n);
        n = (long)H * H;    splitw_kernel<<<(int)((n + 255) / 256), 256>>>(W_rec, wrh, wrl, n);
        n = (long)DOUT * H; splitw_kernel<<<(int)((n + 255) / 256), 256>>>(W_out, woh, wol, n);
    }

    // x_proj = x @ (W_in/s)^T + b_in   (3-term)
    mma_gemm<2, 2, false><<<dim3(H / 128, B / 128), 256, SMEM_XPROJ>>>(
        xhi, xlo, wih, wil, b_in, invsig + 0, DIN, H,
        xproj, nullptr, nullptr, nullptr, 0.0f, 0, nullptr);

    // step 0
    {
        long total = (long)B * H;
        float mod0 = (float)(1.0 + 0.1 * sin(0.0));
        step0_kernel<<<(int)((total + 255) / 256), 256>>>(
            xproj, b_rec, hb[0], total, H, mod0, steps);
    }

    // steps 1..29 (single-MMA, plain fp16 weights)
    int cur = 0;
    for (int t = 1; t < NSTEPS; t++) {
        float mod = (float)(1.0 + 0.1 * sin(0.3 * (double)t));
        mma_gemm<1, 1, true><<<dim3(H / 128, B / 128), 256, SMEM_STEP>>>(
            hb[cur], nullptr, wrh, nullptr, b_rec, invsig + 1, H, H,
            nullptr, hb[1 - cur], xproj, hb[cur], mod, t, steps);
        cur ^= 1;
    }

    // out = h @ (W_out/s)^T + b_out   (2-term, weight-exact)
    mma_gemm<1, 2, false><<<dim3(DOUT / 128, B / 128), 256, SMEM_OUT>>>(
        hb[cur], nullptr, woh, wol, b_out, invsig + 2, H, DOUT,
        (float*)d_out, nullptr, nullptr, nullptr, 0.0f, 0, nullptr);
}

// round 6
// speedup vs baseline: 6.6309x; 1.0357x over previous
#include <cuda_runtime.h>
#include <cuda_fp16.h>
#include <math.h>
#include <stdint.h>

// ============================================================================
// HolomorphicEqProp — round 6: persistent 30-step kernel, row-block sync
//   steps : D = A * fp16(W)   single MMA, fp32 accum (budget verified R5)
//   out   : 2-term weight-exact;  xproj : 3-term
// ============================================================================

#define H_DIM   1024
#define B_DIM   4096
#define NSTEPS  30

__device__ __forceinline__ uint32_t smem_u32(const void* p) {
    uint32_t a;
    asm("{ .reg .u64 t; cvta.to.shared.u64 t, %1; cvt.u32.u64 %0, t; }" : "=r"(a) : "l"(p));
    return a;
}
__device__ __forceinline__ void cp_async16(uint32_t saddr, const void* g) {
    asm volatile("cp.async.cg.shared.global [%0], [%1], 16;" :: "r"(saddr), "l"(g));
}
#define CP_COMMIT() asm volatile("cp.async.commit_group;" ::: "memory")
#define CP_WAIT(n)  asm volatile("cp.async.wait_group %0;" :: "n"(n) : "memory")

__device__ __forceinline__ void ldm_x4(uint32_t* r, uint32_t addr) {
    asm volatile("ldmatrix.sync.aligned.m8n8.x4.shared.b16 {%0,%1,%2,%3}, [%4];"
                 : "=r"(r[0]), "=r"(r[1]), "=r"(r[2]), "=r"(r[3]) : "r"(addr));
}
__device__ __forceinline__ void mma16816(float* c, const uint32_t* a, uint32_t b0, uint32_t b1) {
    asm volatile("mma.sync.aligned.m16n8k16.row.col.f32.f16.f16.f32 "
                 "{%0,%1,%2,%3}, {%4,%5,%6,%7}, {%8,%9}, {%0,%1,%2,%3};"
                 : "+f"(c[0]), "+f"(c[1]), "+f"(c[2]), "+f"(c[3])
                 : "r"(a[0]), "r"(a[1]), "r"(a[2]), "r"(a[3]), "r"(b0), "r"(b1));
}
__device__ __forceinline__ uint32_t h2_scale_dn(uint32_t x) {   // * 2^-11 packed
    uint32_t r;
    asm("mul.f16x2 %0, %1, %2;" : "=r"(r) : "r"(x), "r"(0x10001000u));
    return r;
}
__device__ __forceinline__ uint32_t swz(int row, int seg) {
    uint32_t o = ((uint32_t)row << 7) | ((uint32_t)seg << 4);
    return o ^ ((o >> 3) & 0x70);
}
__device__ __forceinline__ int ld_relaxed(const int* p) {
    int v;
    asm volatile("ld.relaxed.gpu.s32 %0, [%1];" : "=r"(v) : "l"(p));
    return v;
}

// ---------------------------------------------------------------------------
// static scratch
// ---------------------------------------------------------------------------
__device__ __half g_xhi[B_DIM * H_DIM], g_xlo[B_DIM * H_DIM];
__device__ __half g_wih[H_DIM * H_DIM], g_wil[H_DIM * H_DIM];
__device__ __half g_wrh[H_DIM * H_DIM], g_wrl[H_DIM * H_DIM];
__device__ __half g_woh[256 * H_DIM],  g_wol[256 * H_DIM];
__device__ float  g_xproj[B_DIM * H_DIM];
__device__ __half g_h[2][B_DIM * H_DIM];
__device__ float  g_y[H_DIM], g_v[H_DIM], g_z[H_DIM], g_invsig[3];
__device__ int    g_cnt[NSTEPS * 32];

// ---------------------------------------------------------------------------
// spectral norm (tiny)
// ---------------------------------------------------------------------------
__device__ __forceinline__ float block_reduce_sum(float v) {
    __shared__ float sh[32];
    int lane = threadIdx.x & 31, w = threadIdx.x >> 5;
    #pragma unroll
    for (int o = 16; o; o >>= 1) v += __shfl_xor_sync(0xffffffffu, v, o);
    if (!lane) sh[w] = v;
    __syncthreads();
    int nw = blockDim.x >> 5;
    v = (threadIdx.x < nw) ? sh[threadIdx.x] : 0.0f;
    if (w == 0) {
        #pragma unroll
        for (int o = 16; o; o >>= 1) v += __shfl_xor_sync(0xffffffffu, v, o);
        if (!lane) sh[0] = v;
    }
    __syncthreads();
    return sh[0];
}

__global__ void zero_kernel(float* p, int n) {
    int i = blockIdx.x * blockDim.x + threadIdx.x;
    if (i < n) p[i] = 0.0f;
}
__global__ void zeroi_kernel(int* p, int n) {
    int i = blockIdx.x * blockDim.x + threadIdx.x;
    if (i < n) p[i] = 0;
}
__global__ void colmv_kernel(const float* __restrict__ W, const float* __restrict__ u,
                             float* __restrict__ y, int R, int C) {
    int c = blockIdx.x * blockDim.x + threadIdx.x;
    if (c >= C) return;
    int per = R / gridDim.y;
    int r0 = blockIdx.y * per;
    int r1 = (blockIdx.y == gridDim.y - 1) ? R : r0 + per;
    float acc = 0.0f;
    for (int r = r0; r < r1; r++) acc += W[(long)r * C + c] * u[r];
    atomicAdd(&y[c], acc);
}
__global__ void normalize_kernel(const float* __restrict__ y, float* __restrict__ v, int n) {
    float ss = 0.0f;
    for (int i = threadIdx.x; i < n; i += blockDim.x) { float t = y[i]; ss += t * t; }
    float tot = block_reduce_sum(ss);
    float scale = 1.0f / (sqrtf(tot) + 1e-12f);
    for (int i = threadIdx.x; i < n; i += blockDim.x) v[i] = y[i] * scale;
}
__global__ void rowmv_kernel(const float* __restrict__ W, const float* __restrict__ v,
                             float* __restrict__ z, int R, int C) {
    int warp = (blockIdx.x * blockDim.x + threadIdx.x) >> 5;
    int lane = threadIdx.x & 31;
    if (warp >= R) return;
    float acc = 0.0f;
    for (int c = lane; c < C; c += 32) acc += W[(long)warp * C + c] * v[c];
    #pragma unroll
    for (int o = 16; o; o >>= 1) acc += __shfl_xor_sync(0xffffffffu, acc, o);
    if (!lane) z[warp] = acc;
}
__global__ void sigma_kernel(const float* __restrict__ z, float* __restrict__ invsig, int n) {
    float ss = 0.0f;
    for (int i = threadIdx.x; i < n; i += blockDim.x) { float t = z[i]; ss += t * t; }
    float tot = block_reduce_sum(ss);
    if (threadIdx.x == 0) {
        float nz = sqrtf(tot);
        invsig[0] = (nz + 1e-12f) / tot;
    }
}
__global__ void splitw_kernel(const float* __restrict__ s, __half* __restrict__ hi,
                              __half* __restrict__ lo, long n) {
    long i = (long)blockIdx.x * blockDim.x + threadIdx.x;
    if (i >= n) return;
    float f = s[i];
    __half h = __float2half_rn(f);
    hi[i] = h;
    lo[i] = __float2half_rn((f - __half2float(h)) * 2048.0f);
}

// ---------------------------------------------------------------------------
// generic fused GEMM (used for xproj 3-term and out 2-term), as round 5
// ---------------------------------------------------------------------------
template <int ATERMS, int BTERMS>
__global__ __launch_bounds__(256, 2)
void mma_gemm(const __half* __restrict__ A1, const __half* __restrict__ A2,
              const __half* __restrict__ B1, const __half* __restrict__ B2,
              const float* __restrict__ bias, const float* __restrict__ invsig,
              int K, int N, float* __restrict__ Cf32) {
    constexpr int NM = ATERMS + BTERMS;
    constexpr int MAT_B = 16384;
    constexpr int STAGE_B = NM * MAT_B;
    constexpr int STAGES = (NM == 2) ? 3 : 2;

    extern __shared__ char sm[];
    const uint32_t sbase = smem_u32(sm);
    const int tid = threadIdx.x, wid = tid >> 5, lane = tid & 31;
    const int bm = blockIdx.y * 128, bn = blockIdx.x * 128;
    const int wm = (wid >> 2) * 64, wn = (wid & 3) * 32;

    const __half* src[4];
    src[0] = A1 + (size_t)bm * K;
    src[1] = B1 + (size_t)bn * K;
    src[2] = (BTERMS == 2) ? (B2 + (size_t)bn * K)
                           : ((ATERMS == 2) ? (A2 + (size_t)bm * K) : src[0]);
    src[3] = (NM == 4) ? (A2 + (size_t)bm * K) : src[0];
    const uint32_t A2_OFF = (BTERMS == 2) ? 3 * MAT_B : 2 * MAT_B;

    float acc[4][4][4];
    #pragma unroll
    for (int mi = 0; mi < 4; mi++)
        #pragma unroll
        for (int ni = 0; ni < 4; ni++)
            #pragma unroll
            for (int k = 0; k < 4; k++) acc[mi][ni][k] = 0.0f;

    auto stage_load = [&](int chunk, int buf) {
        const uint32_t sb = sbase + buf * STAGE_B;
        const int k0 = chunk << 6;
        #pragma unroll
        for (int it = 0; it < 4 * NM; it++) {
            const int flat = it * 256 + tid;
            const int m = flat >> 10;
            const int rem = flat & 1023;
            const int row = rem >> 3, seg = rem & 7;
            cp_async16(sb + m * MAT_B + swz(row, seg),
                       src[m] + (size_t)row * K + k0 + seg * 8);
        }
    };

    const int nch = K >> 6;
    stage_load(0, 0);
    CP_COMMIT();
    if (STAGES == 3) { stage_load(1, 1); CP_COMMIT(); }

    for (int c = 0; c < nch; c++) {
        if (c + STAGES - 1 < nch) {
            stage_load(c + STAGES - 1, (c + STAGES - 1) % STAGES);
            CP_COMMIT();
            if (STAGES == 3) CP_WAIT(2); else CP_WAIT(1);
        } else if (STAGES == 3 && c + 1 < nch) {
            CP_WAIT(1);
        } else {
            CP_WAIT(0);
        }
        __syncthreads();

        const uint32_t sa = sbase + (c % STAGES) * STAGE_B;
        #pragma unroll
        for (int ks = 0; ks < 4; ks++) {
            const int seg = ks * 2 + (lane >> 4);
            uint32_t af[4][4], b1[2][4];
            #pragma unroll
            for (int mi = 0; mi < 4; mi++)
                ldm_x4(af[mi], sa + swz(wm + mi * 16 + (lane & 15), seg));
            #pragma unroll
            for (int nb = 0; nb < 2; nb++)
                ldm_x4(b1[nb], sa + MAT_B + swz(wn + nb * 16 + (lane & 15), seg));
            #pragma unroll
            for (int mi = 0; mi < 4; mi++)
                #pragma unroll
                for (int ni = 0; ni < 4; ni++)
                    mma16816(acc[mi][ni], af[mi],
                             b1[ni >> 1][ni & 1], b1[ni >> 1][(ni & 1) + 2]);
            if (BTERMS == 2) {
                uint32_t b2f[2][4];
                #pragma unroll
                for (int nb = 0; nb < 2; nb++)
                    ldm_x4(b2f[nb], sa + 2 * MAT_B + swz(wn + nb * 16 + (lane & 15), seg));
                #pragma unroll
                for (int mi = 0; mi < 4; mi++)
                    #pragma unroll
                    for (int r = 0; r < 4; r++) af[mi][r] = h2_scale_dn(af[mi][r]);
                #pragma unroll
                for (int mi = 0; mi < 4; mi++)
                    #pragma unroll
                    for (int ni = 0; ni < 4; ni++)
                        mma16816(acc[mi][ni], af[mi],
                                 b2f[ni >> 1][ni & 1], b2f[ni >> 1][(ni & 1) + 2]);
            }
            if (ATERMS == 2) {
                #pragma unroll
                for (int mi = 0; mi < 4; mi++) {
                    ldm_x4(af[mi], sa + A2_OFF + swz(wm + mi * 16 + (lane & 15), seg));
                    #pragma unroll
                    for (int r = 0; r < 4; r++) af[mi][r] = h2_scale_dn(af[mi][r]);
                }
                #pragma unroll
                for (int mi = 0; mi < 4; mi++)
                    #pragma unroll
                    for (int ni = 0; ni < 4; ni++)
                        mma16816(acc[mi][ni], af[mi],
                                 b1[ni >> 1][ni & 1], b1[ni >> 1][(ni & 1) + 2]);
            }
        }
        __syncthreads();
    }

    const float sig = *invsig;
    const int quad = lane >> 2, tq = lane & 3;
    #pragma unroll
    for (int mi = 0; mi < 4; mi++)
        #pragma unroll
        for (int ni = 0; ni < 4; ni++) {
            const int col = bn + wn + ni * 8 + tq * 2;
            const float b0 = bias[col], b1v = bias[col + 1];
            #pragma unroll
            for (int hr = 0; hr < 2; hr++) {
                const int row = bm + wm + mi * 16 + quad + hr * 8;
                const size_t idx = (size_t)row * N + col;
                float2 o;
                o.x = acc[mi][ni][hr * 2 + 0] * sig + b0;
                o.y = acc[mi][ni][hr * 2 + 1] * sig + b1v;
                *(float2*)(Cf32 + idx) = o;
            }
        }
}

// ---------------------------------------------------------------------------
// persistent 30-step kernel. grid (8, 32). cnt[t*32+bm_blk] counts to 8.
// ---------------------------------------------------------------------------
__global__ __launch_bounds__(256, 2)
void step_persistent(__half* __restrict__ hb0, __half* __restrict__ hb1,
                     const __half* __restrict__ W, const float* __restrict__ brec,
                     const float* __restrict__ invsig, const float* __restrict__ xproj,
                     const int* __restrict__ steps, int* __restrict__ cnt) {
    constexpr int MAT_B = 16384;
    constexpr int STAGE_B = 2 * MAT_B;
    extern __shared__ char sm[];
    const uint32_t sbase = smem_u32(sm);

    const int tid = threadIdx.x, wid = tid >> 5, lane = tid & 31;
    const int bnb = blockIdx.x, bmb = blockIdx.y;
    const int bm = bmb * 128, bn = bnb * 128;
    const int wm = (wid >> 2) * 64, wn = (wid & 3) * 32;
    const int st = *steps;
    const float sig = *invsig;

    // ---- t = 0: h0 tile = tanh(xproj + brec * mod0), mod0 = 1 (sin 0 = 0)
    {
        #pragma unroll
        for (int i = 0; i < 32; i++) {
            const int p = i * 256 + tid;                  // pair index
            const int row = p >> 6, col = (p & 63) * 2;
            const size_t idx = (size_t)(bm + row) * H_DIM + bn + col;
            const float2 xp = *(const float2*)(xproj + idx);
            const float2 bb = *(const float2*)(brec + bn + col);
            union { __half h[2]; uint32_t u; } ph;
            if (0 < st) {
                ph.h[0] = __float2half_rn(tanhf(xp.x + bb.x));
                ph.h[1] = __float2half_rn(tanhf(xp.y + bb.y));
            } else {
                ph.h[0] = __float2half_rn(0.0f);
                ph.h[1] = __float2half_rn(0.0f);
            }
            *(uint32_t*)(hb0 + idx) = ph.u;
        }
        __threadfence();
        __syncthreads();
        if (tid == 0) atomicAdd(&cnt[bmb], 1);
    }

    const __half* Bptr = W + (size_t)bn * H_DIM;

    for (int t = 1; t < NSTEPS; t++) {
        const __half* src = ((t & 1) ? hb0 : hb1) + (size_t)bm * H_DIM;
        __half* dst = (t & 1) ? hb1 : hb0;
        const float mod = 1.0f + 0.1f * sinf(0.3f * (float)t);

        // wait for row-block producers of h_{t-1}
        if (tid == 0) {
            const int* c = &cnt[(t - 1) * 32 + bmb];
            while (ld_relaxed(c) < 8) __nanosleep(64);
        }
        __threadfence();          // acquire
        __syncthreads();

        float acc[4][4][4];
        #pragma unroll
        for (int mi = 0; mi < 4; mi++)
            #pragma unroll
            for (int ni = 0; ni < 4; ni++)
                #pragma unroll
                for (int k = 0; k < 4; k++) acc[mi][ni][k] = 0.0f;

        auto stage_load = [&](int chunk, int buf) {
            const uint32_t sb = sbase + buf * STAGE_B;
            const int k0 = chunk << 6;
            #pragma unroll
            for (int it = 0; it < 8; it++) {
                const int flat = it * 256 + tid;
                const int m = flat >> 10;
                const int rem = flat & 1023;
                const int row = rem >> 3, seg = rem & 7;
                const __half* s = m ? Bptr : src;
                cp_async16(sb + m * MAT_B + swz(row, seg),
                           s + (size_t)row * H_DIM + k0 + seg * 8);
            }
        };

        stage_load(0, 0); CP_COMMIT();
        stage_load(1, 1); CP_COMMIT();

        #pragma unroll 1
        for (int c = 0; c < 16; c++) {
            if (c + 2 < 16) { stage_load(c + 2, (c + 2) % 3); CP_COMMIT(); CP_WAIT(2); }
            else if (c + 1 < 16) { CP_WAIT(1); }
            else { CP_WAIT(0); }
            __syncthreads();

            const uint32_t sa = sbase + (c % 3) * STAGE_B;
            #pragma unroll
            for (int ks = 0; ks < 4; ks++) {
                const int seg = ks * 2 + (lane >> 4);
                uint32_t af[4][4], b1[2][4];
                #pragma unroll
                for (int mi = 0; mi < 4; mi++)
                    ldm_x4(af[mi], sa + swz(wm + mi * 16 + (lane & 15), seg));
                #pragma unroll
                for (int nb = 0; nb < 2; nb++)
                    ldm_x4(b1[nb], sa + MAT_B + swz(wn + nb * 16 + (lane & 15), seg));
                #pragma unroll
                for (int mi = 0; mi < 4; mi++)
                    #pragma unroll
                    for (int ni = 0; ni < 4; ni++)
                        mma16816(acc[mi][ni], af[mi],
                                 b1[ni >> 1][ni & 1], b1[ni >> 1][(ni & 1) + 2]);
            }
            __syncthreads();
        }

        // epilogue
        const int quad = lane >> 2, tq = lane & 3;
        #pragma unroll
        for (int mi = 0; mi < 4; mi++)
            #pragma unroll
            for (int ni = 0; ni < 4; ni++) {
                const int col = bn + wn + ni * 8 + tq * 2;
                const float b0 = brec[col], b1v = brec[col + 1];
                #pragma unroll
                for (int hr = 0; hr < 2; hr++) {
                    const int row = bm + wm + mi * 16 + quad + hr * 8;
                    const size_t idx = (size_t)row * H_DIM + col;
                    if (t < st) {
                        const float2 xp = *(const float2*)(xproj + idx);
                        const float v0 = acc[mi][ni][hr * 2] * sig + b0;
                        const float v1 = acc[mi][ni][hr * 2 + 1] * sig + b1v;
                        union { __half h[2]; uint32_t u; } ph;
                        ph.h[0] = __float2half_rn(tanhf(xp.x + v0 * mod));
                        ph.h[1] = __float2half_rn(tanhf(xp.y + v1 * mod));
                        *(uint32_t*)(dst + idx) = ph.u;
                    } else {
                        *(uint32_t*)(dst + idx) =
                            *(const uint32_t*)(src + (size_t)(row - bm) * H_DIM + col);
                    }
                }
            }

        __threadfence();
        __syncthreads();
        if (tid == 0) atomicAdd(&cnt[t * 32 + bmb], 1);
    }
}

// ---------------------------------------------------------------------------
// launch
// ---------------------------------------------------------------------------
extern "C" void kernel_launch(void* const* d_in, const int* in_sizes, int n_in,
                              void* d_out, int out_size) {
    const float* x     = (const float*)d_in[0];
    const float* W_in  = (const float*)d_in[1];
    const float* b_in  = (const float*)d_in[2];
    const float* W_rec = (const float*)d_in[3];
    const float* b_rec = (const float*)d_in[4];
    const float* W_out = (const float*)d_in[5];
    const float* b_out = (const float*)d_in[6];
    const float* u_in  = (const float*)d_in[7];
    const float* u_rec = (const float*)d_in[8];
    const float* u_out = (const float*)d_in[9];
    const int*   steps = (const int*)d_in[10];

    const int H    = in_sizes[2];
    const int DIN  = in_sizes[1] / H;
    const int B    = in_sizes[0] / DIN;
    const int DOUT = in_sizes[6];

    __half *xhi, *xlo, *wih, *wil, *wrh, *wrl, *woh, *wol, *hbuf0;
    float *xproj, *y, *v, *z, *invsig;
    int* cnt;
    cudaGetSymbolAddress((void**)&xhi, g_xhi);   cudaGetSymbolAddress((void**)&xlo, g_xlo);
    cudaGetSymbolAddress((void**)&wih, g_wih);   cudaGetSymbolAddress((void**)&wil, g_wil);
    cudaGetSymbolAddress((void**)&wrh, g_wrh);   cudaGetSymbolAddress((void**)&wrl, g_wrl);
    cudaGetSymbolAddress((void**)&woh, g_woh);   cudaGetSymbolAddress((void**)&wol, g_wol);
    cudaGetSymbolAddress((void**)&hbuf0, g_h);
    cudaGetSymbolAddress((void**)&xproj, g_xproj);
    cudaGetSymbolAddress((void**)&y, g_y); cudaGetSymbolAddress((void**)&v, g_v);
    cudaGetSymbolAddress((void**)&z, g_z); cudaGetSymbolAddress((void**)&invsig, g_invsig);
    cudaGetSymbolAddress((void**)&cnt, g_cnt);

    __half* hb0 = hbuf0;
    __half* hb1 = hbuf0 + (long)B_DIM * H_DIM;

    constexpr int SMEM_STEP  = 3 * 2 * 16384;   // 96KB
    constexpr int SMEM_OUT   = 2 * 3 * 16384;   // 96KB
    constexpr int SMEM_XPROJ = 2 * 4 * 16384;   // 128KB
    cudaFuncSetAttribute(step_persistent,  cudaFuncAttributeMaxDynamicSharedMemorySize, SMEM_STEP);
    cudaFuncSetAttribute(mma_gemm<1, 2>, cudaFuncAttributeMaxDynamicSharedMemorySize, SMEM_OUT);
    cudaFuncSetAttribute(mma_gemm<2, 2>, cudaFuncAttributeMaxDynamicSharedMemorySize, SMEM_XPROJ);

    // spectral sigma
    auto spectral = [&](const float* W, const float* u, int R, int C, int idx) {
        zero_kernel<<<(C + 255) / 256, 256>>>(y, C);
        colmv_kernel<<<dim3((C + 127) / 128, 8), 128>>>(W, u, y, R, C);
        normalize_kernel<<<1, 256>>>(y, v, C);
        rowmv_kernel<<<(R + 7) / 8, 256>>>(W, v, z, R, C);
        sigma_kernel<<<1, 256>>>(z, invsig + idx, R);
    };
    spectral(W_in,  u_in,  H,    DIN, 0);
    spectral(W_rec, u_rec, H,    H,   1);
    spectral(W_out, u_out, DOUT, H,   2);

    // splits
    {
        long n;
        n = (long)B * DIN;  splitw_kernel<<<(int)((n + 255) / 256), 256>>>(x, xhi, xlo, n);
        n = (long)H * DIN;  splitw_kernel<<<(int)((n + 255) / 256), 256>>>(W_in, wih, wil, n);
        n = (long)H * H;    splitw_kernel<<<(int)((n + 255) / 256), 256>>>(W_rec, wrh, wrl, n);
        n = (long)DOUT * H; splitw_kernel<<<(int)((n + 255) / 256), 256>>>(W_out, woh, wol, n);
    }

    // x_proj = x @ (W_in/s)^T + b_in   (3-term)
    mma_gemm<2, 2><<<dim3(H / 128, B / 128), 256, SMEM_XPROJ>>>(
        xhi, xlo, wih, wil, b_in, invsig + 0, DIN, H, xproj);

    // zero arrival counters (every replay), then run all 30 steps persistently
    zeroi_kernel<<<(NSTEPS * 32 + 255) / 256, 256>>>(cnt, NSTEPS * 32);
    step_persistent<<<dim3(H / 128, B / 128), 256, SMEM_STEP>>>(
        hb0, hb1, wrh, b_rec, invsig + 1, xproj, steps, cnt);

    // out = h @ (W_out/s)^T + b_out   (2-term, weight-exact); final h in hb1
    mma_gemm<1, 2><<<dim3(DOUT / 128, B / 128), 256, SMEM_OUT>>>(
        hb1, nullptr, woh, wol, b_out, invsig + 2, H, DOUT, (float*)d_out);
}